// round 3
// baseline (speedup 1.0000x reference)
#include <cuda_runtime.h>
#include <math.h>

#define B_    2
#define T_    2048
#define C_    2048
#define H_    16
#define KVH_  4
#define D_    128
#define M_    (B_*T_)      // 4096

// Scratch (static device globals: allocation-guard safe)
__device__ float g_q[(size_t)B_*T_*H_*D_];     // 32 MB
__device__ float g_k[(size_t)B_*T_*KVH_*D_];   //  8 MB
__device__ float g_v[(size_t)B_*T_*KVH_*D_];   //  8 MB
__device__ float g_att[(size_t)B_*T_*H_*D_];   // 32 MB

// ---------------------------------------------------------------------------
// GEMM: O[M,N] = A[M,K] @ W[N,K]^T   (both row-major, K contiguous)
// 128x128 block tile, BK=16, 256 threads, 8x8 register tile per thread.
// M % 128 == 0, N % 128 == 0, K % 16 == 0 assumed.
// ---------------------------------------------------------------------------
__global__ __launch_bounds__(256) void gemm_nt(const float* __restrict__ A,
                                               const float* __restrict__ W,
                                               float* __restrict__ O,
                                               int M, int N, int K)
{
    __shared__ float As[16][128 + 4];
    __shared__ float Ws[16][128 + 4];

    const int bm = blockIdx.y * 128;
    const int bn = blockIdx.x * 128;
    const int tid = threadIdx.x;
    const int tm = (tid >> 4) << 3;   // 0..120 step 8
    const int tn = (tid & 15) << 3;   // 0..120 step 8

    float acc[8][8];
#pragma unroll
    for (int i = 0; i < 8; i++)
#pragma unroll
        for (int j = 0; j < 8; j++) acc[i][j] = 0.0f;

    const float* Ap = A + (size_t)bm * K;
    const float* Wp = W + (size_t)bn * K;

    for (int k0 = 0; k0 < K; k0 += 16) {
        // load 128x16 tiles of A and W, store transposed [k][m]
#pragma unroll
        for (int u = 0; u < 2; u++) {
            int idx = tid * 2 + u;            // 0..511
            int r   = idx >> 2;               // 0..127
            int c   = (idx & 3) << 2;         // 0,4,8,12
            float4 av = *(const float4*)(Ap + (size_t)r * K + k0 + c);
            As[c + 0][r] = av.x; As[c + 1][r] = av.y;
            As[c + 2][r] = av.z; As[c + 3][r] = av.w;
            float4 wv = *(const float4*)(Wp + (size_t)r * K + k0 + c);
            Ws[c + 0][r] = wv.x; Ws[c + 1][r] = wv.y;
            Ws[c + 2][r] = wv.z; Ws[c + 3][r] = wv.w;
        }
        __syncthreads();

#pragma unroll
        for (int kk = 0; kk < 16; kk++) {
            float a[8], b[8];
            *(float4*)&a[0] = *(const float4*)&As[kk][tm];
            *(float4*)&a[4] = *(const float4*)&As[kk][tm + 4];
            *(float4*)&b[0] = *(const float4*)&Ws[kk][tn];
            *(float4*)&b[4] = *(const float4*)&Ws[kk][tn + 4];
#pragma unroll
            for (int i = 0; i < 8; i++)
#pragma unroll
                for (int j = 0; j < 8; j++)
                    acc[i][j] += a[i] * b[j];
        }
        __syncthreads();
    }

#pragma unroll
    for (int i = 0; i < 8; i++) {
        float4* o = (float4*)(O + (size_t)(bm + tm + i) * N + bn + tn);
        o[0] = make_float4(acc[i][0], acc[i][1], acc[i][2], acc[i][3]);
        o[1] = make_float4(acc[i][4], acc[i][5], acc[i][6], acc[i][7]);
    }
}

// ---------------------------------------------------------------------------
// Fused RoPE + RMSNorm, in place. One warp per head-vector (D=128).
// Lane l owns dims {l, l+32, l+64, l+96}; rotate_half operands are lane-local.
// ---------------------------------------------------------------------------
__global__ __launch_bounds__(256) void rope_rms(float* __restrict__ v,
                                                const float* __restrict__ cosb,
                                                const float* __restrict__ sinb,
                                                int nheads, int total)
{
    int warp = (blockIdx.x * blockDim.x + threadIdx.x) >> 5;
    int lane = threadIdx.x & 31;
    if (warp >= total) return;

    int t = (warp / nheads) % T_;
    float* p = v + (size_t)warp * D_;

    float x0 = p[lane], x1 = p[lane + 32], x2 = p[lane + 64], x3 = p[lane + 96];
    const float* cp = cosb + (size_t)t * D_;
    const float* sp = sinb + (size_t)t * D_;
    float c0 = cp[lane], c1 = cp[lane + 32], c2 = cp[lane + 64], c3 = cp[lane + 96];
    float s0 = sp[lane], s1 = sp[lane + 32], s2 = sp[lane + 64], s3 = sp[lane + 96];

    // rotate_half: out[d] = x[d]*cos[d] + rot[d]*sin[d];
    // rot[d] = -x[d+64] (d<64), x[d-64] (d>=64)
    float r0 = x0 * c0 - x2 * s0;
    float r1 = x1 * c1 - x3 * s1;
    float r2 = x2 * c2 + x0 * s2;
    float r3 = x3 * c3 + x1 * s3;

    float ss = r0 * r0 + r1 * r1 + r2 * r2 + r3 * r3;
#pragma unroll
    for (int off = 16; off; off >>= 1)
        ss += __shfl_xor_sync(0xffffffffu, ss, off);
    float inv = rsqrtf(ss * (1.0f / 128.0f) + 1.1920929e-7f);

    p[lane]      = r0 * inv;
    p[lane + 32] = r1 * inv;
    p[lane + 64] = r2 * inv;
    p[lane + 96] = r3 * inv;
}

// ---------------------------------------------------------------------------
// Causal flash attention, fp32, GQA (kv head = h>>2).
// Block = 64 queries of one (b,h). 64-key tiles, online softmax.
// Smem: Q[64][132] K[64][132] V[64][128] P[64][68] = 117760 B (dynamic).
// Threads 256 as 16x16: thread owns S 4x4, O 4x8.
// ---------------------------------------------------------------------------
#define ATT_SMEM_BYTES ((64*132*2 + 64*128 + 64*68) * 4)

__global__ __launch_bounds__(256) void attn_kernel()
{
    extern __shared__ float sm[];
    float* Qs = sm;                 // pitch 132
    float* Ks = Qs + 64 * 132;      // pitch 132
    float* Vs = Ks + 64 * 132;      // pitch 128
    float* Ps = Vs + 64 * 128;      // pitch 68

    const int qt = blockIdx.x, h = blockIdx.y, b = blockIdx.z;
    const int kvh = h >> 2;
    const int q0  = qt * 64;
    const int tid = threadIdx.x;
    const int ti  = tid >> 4, tj = tid & 15;
    const float scale = 0.08838834764831845f;  // 1/sqrt(128)

    // load Q tile
#pragma unroll
    for (int u = 0; u < 8; u++) {
        int fl = tid + u * 256;            // 0..2047
        int r = fl >> 5, c = (fl & 31) << 2;
        const float* src = g_q + ((size_t)((b * T_ + q0 + r) * H_ + h)) * D_ + c;
        *(float4*)&Qs[r * 132 + c] = *(const float4*)src;
    }

    float m_i[4], l_i[4], Ot[4][8];
#pragma unroll
    for (int a = 0; a < 4; a++) {
        m_i[a] = -1e30f; l_i[a] = 0.0f;
#pragma unroll
        for (int c = 0; c < 8; c++) Ot[a][c] = 0.0f;
    }

    for (int jt = 0; jt <= qt; jt++) {
        const int j0 = jt * 64;
        // load K,V tiles
#pragma unroll
        for (int u = 0; u < 8; u++) {
            int fl = tid + u * 256;
            int r = fl >> 5, c = (fl & 31) << 2;
            size_t base = ((size_t)((b * T_ + j0 + r) * KVH_ + kvh)) * D_ + c;
            *(float4*)&Ks[r * 132 + c] = *(const float4*)(g_k + base);
            *(float4*)&Vs[r * 128 + c] = *(const float4*)(g_v + base);
        }
        __syncthreads();

        // S = Q K^T  (4x4 per thread)
        float s[4][4] = {};
#pragma unroll 4
        for (int d = 0; d < 128; d += 4) {
            float4 qv[4], kv[4];
#pragma unroll
            for (int a = 0; a < 4; a++)
                qv[a] = *(const float4*)&Qs[(ti * 4 + a) * 132 + d];
#pragma unroll
            for (int bb = 0; bb < 4; bb++)
                kv[bb] = *(const float4*)&Ks[(tj * 4 + bb) * 132 + d];
#pragma unroll
            for (int a = 0; a < 4; a++)
#pragma unroll
                for (int bb = 0; bb < 4; bb++)
                    s[a][bb] += qv[a].x * kv[bb].x + qv[a].y * kv[bb].y +
                                qv[a].z * kv[bb].z + qv[a].w * kv[bb].w;
        }

        // scale + causal mask + online softmax (row = 16-lane group reduce)
#pragma unroll
        for (int a = 0; a < 4; a++) {
            int qi = q0 + ti * 4 + a;
            float mloc = -1e30f;
#pragma unroll
            for (int bb = 0; bb < 4; bb++) {
                int kj = j0 + tj * 4 + bb;
                float val = (kj <= qi) ? s[a][bb] * scale : -1e30f;
                s[a][bb] = val;
                mloc = fmaxf(mloc, val);
            }
#pragma unroll
            for (int off = 8; off; off >>= 1)
                mloc = fmaxf(mloc, __shfl_xor_sync(0xffffffffu, mloc, off));
            float mnew  = fmaxf(m_i[a], mloc);
            float alpha = __expf(m_i[a] - mnew);
            float rsum  = 0.0f;
#pragma unroll
            for (int bb = 0; bb < 4; bb++) {
                float pv = __expf(s[a][bb] - mnew);
                s[a][bb] = pv;
                rsum += pv;
            }
#pragma unroll
            for (int off = 8; off; off >>= 1)
                rsum += __shfl_xor_sync(0xffffffffu, rsum, off);
            l_i[a] = l_i[a] * alpha + rsum;
            m_i[a] = mnew;
#pragma unroll
            for (int c = 0; c < 8; c++) Ot[a][c] *= alpha;
#pragma unroll
            for (int bb = 0; bb < 4; bb++)
                Ps[(ti * 4 + a) * 68 + tj * 4 + bb] = s[a][bb];
        }
        __syncthreads();

        // O += P V   (thread owns rows ti*4+a, cols tj*8..tj*8+7)
#pragma unroll 4
        for (int j = 0; j < 64; j++) {
            float4 v0 = *(const float4*)&Vs[j * 128 + tj * 8];
            float4 v1 = *(const float4*)&Vs[j * 128 + tj * 8 + 4];
#pragma unroll
            for (int a = 0; a < 4; a++) {
                float pv = Ps[(ti * 4 + a) * 68 + j];
                Ot[a][0] += pv * v0.x; Ot[a][1] += pv * v0.y;
                Ot[a][2] += pv * v0.z; Ot[a][3] += pv * v0.w;
                Ot[a][4] += pv * v1.x; Ot[a][5] += pv * v1.y;
                Ot[a][6] += pv * v1.z; Ot[a][7] += pv * v1.w;
            }
        }
        __syncthreads();
    }

    // epilogue: normalize, write [B,T,H,D]
#pragma unroll
    for (int a = 0; a < 4; a++) {
        float inv = 1.0f / l_i[a];
        int qi = q0 + ti * 4 + a;
        float* dst = g_att + ((size_t)((b * T_ + qi) * H_ + h)) * D_ + tj * 8;
        *(float4*)dst       = make_float4(Ot[a][0] * inv, Ot[a][1] * inv,
                                          Ot[a][2] * inv, Ot[a][3] * inv);
        *(float4*)(dst + 4) = make_float4(Ot[a][4] * inv, Ot[a][5] * inv,
                                          Ot[a][6] * inv, Ot[a][7] * inv);
    }
}

// ---------------------------------------------------------------------------
extern "C" void kernel_launch(void* const* d_in, const int* in_sizes, int n_in,
                              void* d_out, int out_size)
{
    const float* x    = (const float*)d_in[0];
    const float* cosb = (const float*)d_in[1];
    const float* sinb = (const float*)d_in[2];
    const float* wq   = (const float*)d_in[3];
    const float* wk   = (const float*)d_in[4];
    const float* wv   = (const float*)d_in[5];
    const float* wp   = (const float*)d_in[6];
    float* out = (float*)d_out;

    float *q, *k, *v, *att;
    cudaGetSymbolAddress((void**)&q,   g_q);
    cudaGetSymbolAddress((void**)&k,   g_k);
    cudaGetSymbolAddress((void**)&v,   g_v);
    cudaGetSymbolAddress((void**)&att, g_att);

    cudaFuncSetAttribute(attn_kernel,
                         cudaFuncAttributeMaxDynamicSharedMemorySize,
                         ATT_SMEM_BYTES);

    // QKV projections
    gemm_nt<<<dim3(C_ / 128, M_ / 128), 256>>>(x, wq, q, M_, H_ * D_,   C_);
    gemm_nt<<<dim3((KVH_*D_) / 128, M_ / 128), 256>>>(x, wk, k, M_, KVH_ * D_, C_);
    gemm_nt<<<dim3((KVH_*D_) / 128, M_ / 128), 256>>>(x, wv, v, M_, KVH_ * D_, C_);

    // RoPE + RMSNorm (in place)
    {
        int totq = B_ * T_ * H_;
        int totk = B_ * T_ * KVH_;
        rope_rms<<<(totq + 7) / 8, 256>>>(q, cosb, sinb, H_,   totq);
        rope_rms<<<(totk + 7) / 8, 256>>>(k, cosb, sinb, KVH_, totk);
    }

    // Flash attention
    attn_kernel<<<dim3(T_ / 64, H_, B_), 256, ATT_SMEM_BYTES>>>();

    // Output projection
    gemm_nt<<<dim3(C_ / 128, M_ / 128), 256>>>(att, wp, out, M_, C_, C_);
}

// round 7
// speedup vs baseline: 1.3581x; 1.3581x over previous
#include <cuda_runtime.h>
#include <cuda_bf16.h>
#include <cstdint>
#include <math.h>

#define B_    2
#define T_    2048
#define C_    2048
#define H_    16
#define KVH_  4
#define D_    128
#define M_    (B_*T_)      // 4096

// ---------------------------------------------------------------------------
// Scratch (static device globals: allocation-guard safe)
// ---------------------------------------------------------------------------
__device__ float g_q[(size_t)B_*T_*H_*D_];     // 32 MB
__device__ float g_k[(size_t)B_*T_*KVH_*D_];   //  8 MB
__device__ float g_v[(size_t)B_*T_*KVH_*D_];   //  8 MB
__device__ float g_att[(size_t)B_*T_*H_*D_];   // 32 MB

// bf16 split buffers (hi + lo, x = hi + lo with ~16 mantissa bits)
__device__ __nv_bfloat16 g_xh[(size_t)M_*C_];   // reused for att after attention
__device__ __nv_bfloat16 g_xl[(size_t)M_*C_];
__device__ __nv_bfloat16 g_wqh[(size_t)2048*2048], g_wql[(size_t)2048*2048];
__device__ __nv_bfloat16 g_wkh[(size_t)512*2048],  g_wkl[(size_t)512*2048];
__device__ __nv_bfloat16 g_wvh[(size_t)512*2048],  g_wvl[(size_t)512*2048];
__device__ __nv_bfloat16 g_wph[(size_t)2048*2048], g_wpl[(size_t)2048*2048];

// ---------------------------------------------------------------------------
// mma.sync helpers (sm_80-era PTX: compiles for plain compute_103)
// ---------------------------------------------------------------------------
static __device__ __forceinline__ uint32_t s2u(const void* p) {
    return (uint32_t)__cvta_generic_to_shared(p);
}
static __device__ __forceinline__ void ldm_x4(uint32_t* r, uint32_t addr) {
    asm volatile("ldmatrix.sync.aligned.m8n8.x4.shared.b16 {%0,%1,%2,%3}, [%4];"
                 : "=r"(r[0]), "=r"(r[1]), "=r"(r[2]), "=r"(r[3]) : "r"(addr));
}
static __device__ __forceinline__ void mma_bf16(float* d, const uint32_t* a,
                                                uint32_t b0, uint32_t b1) {
    asm volatile(
        "mma.sync.aligned.m16n8k16.row.col.f32.bf16.bf16.f32 "
        "{%0,%1,%2,%3}, {%4,%5,%6,%7}, {%8,%9}, {%0,%1,%2,%3};"
        : "+f"(d[0]), "+f"(d[1]), "+f"(d[2]), "+f"(d[3])
        : "r"(a[0]), "r"(a[1]), "r"(a[2]), "r"(a[3]), "r"(b0), "r"(b1));
}

// ---------------------------------------------------------------------------
// fp32 -> bf16 hi/lo split. n must be a multiple of 1024. 256 thr * 4 elem.
// ---------------------------------------------------------------------------
__global__ __launch_bounds__(256) void split_bf16(const float* __restrict__ src,
                                                  __nv_bfloat16* __restrict__ hi,
                                                  __nv_bfloat16* __restrict__ lo,
                                                  int n)
{
    int i = (blockIdx.x * 256 + threadIdx.x) * 4;
    if (i >= n) return;
    float4 v = *(const float4*)(src + i);
    __nv_bfloat16 h0 = __float2bfloat16(v.x);
    __nv_bfloat16 h1 = __float2bfloat16(v.y);
    __nv_bfloat16 h2 = __float2bfloat16(v.z);
    __nv_bfloat16 h3 = __float2bfloat16(v.w);
    __nv_bfloat16 l0 = __float2bfloat16(v.x - __bfloat162float(h0));
    __nv_bfloat16 l1 = __float2bfloat16(v.y - __bfloat162float(h1));
    __nv_bfloat16 l2 = __float2bfloat16(v.z - __bfloat162float(h2));
    __nv_bfloat16 l3 = __float2bfloat16(v.w - __bfloat162float(h3));
    __nv_bfloat162 ph0; ph0.x = h0; ph0.y = h1;
    __nv_bfloat162 ph1; ph1.x = h2; ph1.y = h3;
    __nv_bfloat162 pl0; pl0.x = l0; pl0.y = l1;
    __nv_bfloat162 pl1; pl1.x = l2; pl1.y = l3;
    *(__nv_bfloat162*)(hi + i)     = ph0;
    *(__nv_bfloat162*)(hi + i + 2) = ph1;
    *(__nv_bfloat162*)(lo + i)     = pl0;
    *(__nv_bfloat162*)(lo + i + 2) = pl1;
}

// ---------------------------------------------------------------------------
// bf16x3 HMMA GEMM: O[M,N] = (Ah+Al)[M,K] @ (Wh+Wl)[N,K]^T  (fp32 out)
// CTA 128x128, BK=32. 256 thr = 8 warps (4x2); warp tile 32x64.
// mma.m16n8k16 row.col: A row-major [m][k], B = W[n][k] (col-major KxN).
// 3 accumulating passes: hh, hl, lh.
// ---------------------------------------------------------------------------
#define APITCH 40   // halves; 80 bytes (16B aligned)

__global__ __launch_bounds__(256) void gemm_mma(
    const __nv_bfloat16* __restrict__ Ah, const __nv_bfloat16* __restrict__ Al,
    const __nv_bfloat16* __restrict__ Wh, const __nv_bfloat16* __restrict__ Wl,
    float* __restrict__ O, int N, int K)
{
    __shared__ __nv_bfloat16 sAh[128][APITCH], sAl[128][APITCH];
    __shared__ __nv_bfloat16 sWh[128][APITCH], sWl[128][APITCH];

    const int tid  = threadIdx.x;
    const int lane = tid & 31, wid = tid >> 5;
    const int wm = wid >> 1, wn = wid & 1;          // 4x2 warp grid
    const int bm = blockIdx.y * 128, bn = blockIdx.x * 128;

    float acc[2][8][4];
#pragma unroll
    for (int mi = 0; mi < 2; mi++)
#pragma unroll
        for (int ni = 0; ni < 8; ni++)
#pragma unroll
            for (int e = 0; e < 4; e++) acc[mi][ni][e] = 0.0f;

    const __nv_bfloat16* pAh = Ah + (size_t)bm * K;
    const __nv_bfloat16* pAl = Al + (size_t)bm * K;
    const __nv_bfloat16* pWh = Wh + (size_t)bn * K;
    const __nv_bfloat16* pWl = Wl + (size_t)bn * K;

    // ldmatrix source addresses (constant across k-chunks up to offsets)
    const int ar = lane & 15, ac = (lane >> 4) << 3;             // A frag pattern
    const int bn_off = ((lane >> 4) << 3) + (lane & 7);          // B frag pattern
    const int bk_off = ((lane >> 3) & 1) << 3;

    for (int k0 = 0; k0 < K; k0 += 32) {
        // ---- load 128x32 chunks of all four operands ----
#pragma unroll
        for (int u = 0; u < 2; u++) {
            int r  = (tid >> 2) + u * 64;       // 0..127
            int cb = (tid & 3) << 3;            // 0,8,16,24 halves (16B)
            size_t go = (size_t)r * K + k0 + cb;
            *(float4*)&sAh[r][cb] = *(const float4*)(pAh + go);
            *(float4*)&sAl[r][cb] = *(const float4*)(pAl + go);
            *(float4*)&sWh[r][cb] = *(const float4*)(pWh + go);
            *(float4*)&sWl[r][cb] = *(const float4*)(pWl + go);
        }
        __syncthreads();

#pragma unroll
        for (int ks = 0; ks < 2; ks++) {
            const int kk = ks * 16;
            uint32_t ah[2][4], al[2][4];
#pragma unroll
            for (int mi = 0; mi < 2; mi++) {
                int row = wm * 32 + mi * 16 + ar;
                ldm_x4(ah[mi], s2u(&sAh[row][kk + ac]));
                ldm_x4(al[mi], s2u(&sAl[row][kk + ac]));
            }
#pragma unroll
            for (int np = 0; np < 4; np++) {
                uint32_t bh[4], bl[4];
                int row = wn * 64 + np * 16 + bn_off;
                ldm_x4(bh, s2u(&sWh[row][kk + bk_off]));
                ldm_x4(bl, s2u(&sWl[row][kk + bk_off]));
#pragma unroll
                for (int mi = 0; mi < 2; mi++) {
                    mma_bf16(acc[mi][np*2],   ah[mi], bh[0], bh[1]);  // hh
                    mma_bf16(acc[mi][np*2+1], ah[mi], bh[2], bh[3]);
                    mma_bf16(acc[mi][np*2],   ah[mi], bl[0], bl[1]);  // hl
                    mma_bf16(acc[mi][np*2+1], ah[mi], bl[2], bl[3]);
                    mma_bf16(acc[mi][np*2],   al[mi], bh[0], bh[1]);  // lh
                    mma_bf16(acc[mi][np*2+1], al[mi], bh[2], bh[3]);
                }
            }
        }
        __syncthreads();
    }

    // ---- epilogue: d0,d1 -> (row, col..col+1); d2,d3 -> (row+8, ...) ----
#pragma unroll
    for (int mi = 0; mi < 2; mi++) {
#pragma unroll
        for (int ni = 0; ni < 8; ni++) {
            int row = bm + wm * 32 + mi * 16 + (lane >> 2);
            int col = bn + wn * 64 + ni * 8 + ((lane & 3) << 1);
            float2* o0 = (float2*)(O + (size_t)row * N + col);
            float2* o1 = (float2*)(O + (size_t)(row + 8) * N + col);
            *o0 = make_float2(acc[mi][ni][0], acc[mi][ni][1]);
            *o1 = make_float2(acc[mi][ni][2], acc[mi][ni][3]);
        }
    }
}

// ---------------------------------------------------------------------------
// Fused RoPE + RMSNorm, in place. One warp per head-vector (D=128).
// ---------------------------------------------------------------------------
__global__ __launch_bounds__(256) void rope_rms(float* __restrict__ v,
                                                const float* __restrict__ cosb,
                                                const float* __restrict__ sinb,
                                                int nheads, int total)
{
    int warp = (blockIdx.x * blockDim.x + threadIdx.x) >> 5;
    int lane = threadIdx.x & 31;
    if (warp >= total) return;

    int t = (warp / nheads) % T_;
    float* p = v + (size_t)warp * D_;

    float x0 = p[lane], x1 = p[lane + 32], x2 = p[lane + 64], x3 = p[lane + 96];
    const float* cp = cosb + (size_t)t * D_;
    const float* sp = sinb + (size_t)t * D_;
    float c0 = cp[lane], c1 = cp[lane + 32], c2 = cp[lane + 64], c3 = cp[lane + 96];
    float s0 = sp[lane], s1 = sp[lane + 32], s2 = sp[lane + 64], s3 = sp[lane + 96];

    float r0 = x0 * c0 - x2 * s0;
    float r1 = x1 * c1 - x3 * s1;
    float r2 = x2 * c2 + x0 * s2;
    float r3 = x3 * c3 + x1 * s3;

    float ss = r0 * r0 + r1 * r1 + r2 * r2 + r3 * r3;
#pragma unroll
    for (int off = 16; off; off >>= 1)
        ss += __shfl_xor_sync(0xffffffffu, ss, off);
    float inv = rsqrtf(ss * (1.0f / 128.0f) + 1.1920929e-7f);

    p[lane]      = r0 * inv;
    p[lane + 32] = r1 * inv;
    p[lane + 64] = r2 * inv;
    p[lane + 96] = r3 * inv;
}

// ---------------------------------------------------------------------------
// Causal flash attention, fp32, GQA (kv head = h>>2).
// ---------------------------------------------------------------------------
#define ATT_SMEM_BYTES ((64*132*2 + 64*128 + 64*68) * 4)

__global__ __launch_bounds__(256) void attn_kernel()
{
    extern __shared__ float sm[];
    float* Qs = sm;                 // pitch 132
    float* Ks = Qs + 64 * 132;      // pitch 132
    float* Vs = Ks + 64 * 132;      // pitch 128
    float* Ps = Vs + 64 * 128;      // pitch 68

    const int qt = blockIdx.x, h = blockIdx.y, b = blockIdx.z;
    const int kvh = h >> 2;
    const int q0  = qt * 64;
    const int tid = threadIdx.x;
    const int ti  = tid >> 4, tj = tid & 15;
    const float scale = 0.08838834764831845f;  // 1/sqrt(128)

#pragma unroll
    for (int u = 0; u < 8; u++) {
        int fl = tid + u * 256;
        int r = fl >> 5, c = (fl & 31) << 2;
        const float* src = g_q + ((size_t)((b * T_ + q0 + r) * H_ + h)) * D_ + c;
        *(float4*)&Qs[r * 132 + c] = *(const float4*)src;
    }

    float m_i[4], l_i[4], Ot[4][8];
#pragma unroll
    for (int a = 0; a < 4; a++) {
        m_i[a] = -1e30f; l_i[a] = 0.0f;
#pragma unroll
        for (int c = 0; c < 8; c++) Ot[a][c] = 0.0f;
    }

    for (int jt = 0; jt <= qt; jt++) {
        const int j0 = jt * 64;
#pragma unroll
        for (int u = 0; u < 8; u++) {
            int fl = tid + u * 256;
            int r = fl >> 5, c = (fl & 31) << 2;
            size_t base = ((size_t)((b * T_ + j0 + r) * KVH_ + kvh)) * D_ + c;
            *(float4*)&Ks[r * 132 + c] = *(const float4*)(g_k + base);
            *(float4*)&Vs[r * 128 + c] = *(const float4*)(g_v + base);
        }
        __syncthreads();

        float s[4][4] = {};
#pragma unroll 4
        for (int d = 0; d < 128; d += 4) {
            float4 qv[4], kv[4];
#pragma unroll
            for (int a = 0; a < 4; a++)
                qv[a] = *(const float4*)&Qs[(ti * 4 + a) * 132 + d];
#pragma unroll
            for (int bb = 0; bb < 4; bb++)
                kv[bb] = *(const float4*)&Ks[(tj * 4 + bb) * 132 + d];
#pragma unroll
            for (int a = 0; a < 4; a++)
#pragma unroll
                for (int bb = 0; bb < 4; bb++)
                    s[a][bb] += qv[a].x * kv[bb].x + qv[a].y * kv[bb].y +
                                qv[a].z * kv[bb].z + qv[a].w * kv[bb].w;
        }

#pragma unroll
        for (int a = 0; a < 4; a++) {
            int qi = q0 + ti * 4 + a;
            float mloc = -1e30f;
#pragma unroll
            for (int bb = 0; bb < 4; bb++) {
                int kj = j0 + tj * 4 + bb;
                float val = (kj <= qi) ? s[a][bb] * scale : -1e30f;
                s[a][bb] = val;
                mloc = fmaxf(mloc, val);
            }
#pragma unroll
            for (int off = 8; off; off >>= 1)
                mloc = fmaxf(mloc, __shfl_xor_sync(0xffffffffu, mloc, off));
            float mnew  = fmaxf(m_i[a], mloc);
            float alpha = __expf(m_i[a] - mnew);
            float rsum  = 0.0f;
#pragma unroll
            for (int bb = 0; bb < 4; bb++) {
                float pv = __expf(s[a][bb] - mnew);
                s[a][bb] = pv;
                rsum += pv;
            }
#pragma unroll
            for (int off = 8; off; off >>= 1)
                rsum += __shfl_xor_sync(0xffffffffu, rsum, off);
            l_i[a] = l_i[a] * alpha + rsum;
            m_i[a] = mnew;
#pragma unroll
            for (int c = 0; c < 8; c++) Ot[a][c] *= alpha;
#pragma unroll
            for (int bb = 0; bb < 4; bb++)
                Ps[(ti * 4 + a) * 68 + tj * 4 + bb] = s[a][bb];
        }
        __syncthreads();

#pragma unroll 4
        for (int j = 0; j < 64; j++) {
            float4 v0 = *(const float4*)&Vs[j * 128 + tj * 8];
            float4 v1 = *(const float4*)&Vs[j * 128 + tj * 8 + 4];
#pragma unroll
            for (int a = 0; a < 4; a++) {
                float pv = Ps[(ti * 4 + a) * 68 + j];
                Ot[a][0] += pv * v0.x; Ot[a][1] += pv * v0.y;
                Ot[a][2] += pv * v0.z; Ot[a][3] += pv * v0.w;
                Ot[a][4] += pv * v1.x; Ot[a][5] += pv * v1.y;
                Ot[a][6] += pv * v1.z; Ot[a][7] += pv * v1.w;
            }
        }
        __syncthreads();
    }

#pragma unroll
    for (int a = 0; a < 4; a++) {
        float inv = 1.0f / l_i[a];
        int qi = q0 + ti * 4 + a;
        float* dst = g_att + ((size_t)((b * T_ + qi) * H_ + h)) * D_ + tj * 8;
        *(float4*)dst       = make_float4(Ot[a][0] * inv, Ot[a][1] * inv,
                                          Ot[a][2] * inv, Ot[a][3] * inv);
        *(float4*)(dst + 4) = make_float4(Ot[a][4] * inv, Ot[a][5] * inv,
                                          Ot[a][6] * inv, Ot[a][7] * inv);
    }
}

// ---------------------------------------------------------------------------
extern "C" void kernel_launch(void* const* d_in, const int* in_sizes, int n_in,
                              void* d_out, int out_size)
{
    const float* x    = (const float*)d_in[0];
    const float* cosb = (const float*)d_in[1];
    const float* sinb = (const float*)d_in[2];
    const float* wq   = (const float*)d_in[3];
    const float* wk   = (const float*)d_in[4];
    const float* wv   = (const float*)d_in[5];
    const float* wp   = (const float*)d_in[6];
    float* out = (float*)d_out;

    float *q, *k, *v, *att;
    cudaGetSymbolAddress((void**)&q,   g_q);
    cudaGetSymbolAddress((void**)&k,   g_k);
    cudaGetSymbolAddress((void**)&v,   g_v);
    cudaGetSymbolAddress((void**)&att, g_att);

    __nv_bfloat16 *xh, *xl, *wqh, *wql, *wkh, *wkl, *wvh, *wvl, *wph, *wpl;
    cudaGetSymbolAddress((void**)&xh,  g_xh);
    cudaGetSymbolAddress((void**)&xl,  g_xl);
    cudaGetSymbolAddress((void**)&wqh, g_wqh);
    cudaGetSymbolAddress((void**)&wql, g_wql);
    cudaGetSymbolAddress((void**)&wkh, g_wkh);
    cudaGetSymbolAddress((void**)&wkl, g_wkl);
    cudaGetSymbolAddress((void**)&wvh, g_wvh);
    cudaGetSymbolAddress((void**)&wvl, g_wvl);
    cudaGetSymbolAddress((void**)&wph, g_wph);
    cudaGetSymbolAddress((void**)&wpl, g_wpl);

    cudaFuncSetAttribute(attn_kernel,
                         cudaFuncAttributeMaxDynamicSharedMemorySize, ATT_SMEM_BYTES);

    // fp32 -> bf16 hi/lo splits
    split_bf16<<<(M_*C_) / 1024, 256>>>(x,  xh,  xl,  M_*C_);
    split_bf16<<<(2048*2048) / 1024, 256>>>(wq, wqh, wql, 2048*2048);
    split_bf16<<<(512*2048) / 1024, 256>>>(wk, wkh, wkl, 512*2048);
    split_bf16<<<(512*2048) / 1024, 256>>>(wv, wvh, wvl, 512*2048);
    split_bf16<<<(2048*2048) / 1024, 256>>>(wp, wph, wpl, 2048*2048);

    // QKV projections (HMMA bf16x3)
    gemm_mma<<<dim3(2048/128, M_/128), 256>>>(xh, xl, wqh, wql, q, 2048, C_);
    gemm_mma<<<dim3(512/128,  M_/128), 256>>>(xh, xl, wkh, wkl, k, 512,  C_);
    gemm_mma<<<dim3(512/128,  M_/128), 256>>>(xh, xl, wvh, wvl, v, 512,  C_);

    // RoPE + RMSNorm (in place, fp32)
    {
        int totq = B_ * T_ * H_;
        int totk = B_ * T_ * KVH_;
        rope_rms<<<(totq + 7) / 8, 256>>>(q, cosb, sinb, H_,   totq);
        rope_rms<<<(totk + 7) / 8, 256>>>(k, cosb, sinb, KVH_, totk);
    }

    // Flash attention (fp32)
    attn_kernel<<<dim3(T_ / 64, H_, B_), 256, ATT_SMEM_BYTES>>>();

    // Output projection: split attention output (reuse x split buffers), then GEMM
    split_bf16<<<(M_*C_) / 1024, 256>>>(att, xh, xl, M_*C_);
    gemm_mma<<<dim3(2048/128, M_/128), 256>>>(xh, xl, wph, wpl, out, 2048, C_);
}

// round 9
// speedup vs baseline: 1.8937x; 1.3943x over previous
#include <cuda_runtime.h>
#include <cuda_bf16.h>
#include <cstdint>
#include <math.h>

#define B_    2
#define T_    2048
#define C_    2048
#define H_    16
#define KVH_  4
#define D_    128
#define M_    (B_*T_)      // 4096

// ---------------------------------------------------------------------------
// Scratch (static device globals: allocation-guard safe)
// ---------------------------------------------------------------------------
__device__ float g_q[(size_t)B_*T_*H_*D_];     // 32 MB
__device__ float g_k[(size_t)B_*T_*KVH_*D_];   //  8 MB
__device__ float g_v[(size_t)B_*T_*KVH_*D_];   //  8 MB
__device__ float g_att[(size_t)B_*T_*H_*D_];   // 32 MB

// bf16 split buffers (hi + lo, x = hi + lo with ~16 mantissa bits)
__device__ __nv_bfloat16 g_xh[(size_t)M_*C_];   // reused for att after attention
__device__ __nv_bfloat16 g_xl[(size_t)M_*C_];
__device__ __nv_bfloat16 g_wqh[(size_t)2048*2048], g_wql[(size_t)2048*2048];
__device__ __nv_bfloat16 g_wkh[(size_t)512*2048],  g_wkl[(size_t)512*2048];
__device__ __nv_bfloat16 g_wvh[(size_t)512*2048],  g_wvl[(size_t)512*2048];
__device__ __nv_bfloat16 g_wph[(size_t)2048*2048], g_wpl[(size_t)2048*2048];

// ---------------------------------------------------------------------------
// mma.sync helpers (sm_80-era PTX: compiles for plain compute_103)
// ---------------------------------------------------------------------------
static __device__ __forceinline__ uint32_t s2u(const void* p) {
    return (uint32_t)__cvta_generic_to_shared(p);
}
static __device__ __forceinline__ void ldm_x4(uint32_t* r, uint32_t addr) {
    asm volatile("ldmatrix.sync.aligned.m8n8.x4.shared.b16 {%0,%1,%2,%3}, [%4];"
                 : "=r"(r[0]), "=r"(r[1]), "=r"(r[2]), "=r"(r[3]) : "r"(addr));
}
static __device__ __forceinline__ void ldm_x4_t(uint32_t* r, uint32_t addr) {
    asm volatile("ldmatrix.sync.aligned.m8n8.x4.trans.shared.b16 {%0,%1,%2,%3}, [%4];"
                 : "=r"(r[0]), "=r"(r[1]), "=r"(r[2]), "=r"(r[3]) : "r"(addr));
}
static __device__ __forceinline__ void mma_bf16(float* d, const uint32_t* a,
                                                uint32_t b0, uint32_t b1) {
    asm volatile(
        "mma.sync.aligned.m16n8k16.row.col.f32.bf16.bf16.f32 "
        "{%0,%1,%2,%3}, {%4,%5,%6,%7}, {%8,%9}, {%0,%1,%2,%3};"
        : "+f"(d[0]), "+f"(d[1]), "+f"(d[2]), "+f"(d[3])
        : "r"(a[0]), "r"(a[1]), "r"(a[2]), "r"(a[3]), "r"(b0), "r"(b1));
}
// pack two floats as bf16x2 hi/lo split
static __device__ __forceinline__ void split2(float x, float y,
                                              uint32_t& hi, uint32_t& lo) {
    __nv_bfloat16 hx = __float2bfloat16(x), hy = __float2bfloat16(y);
    __nv_bfloat16 lx = __float2bfloat16(x - __bfloat162float(hx));
    __nv_bfloat16 ly = __float2bfloat16(y - __bfloat162float(hy));
    __nv_bfloat162 Hp; Hp.x = hx; Hp.y = hy;
    __nv_bfloat162 Lp; Lp.x = lx; Lp.y = ly;
    hi = *reinterpret_cast<uint32_t*>(&Hp);
    lo = *reinterpret_cast<uint32_t*>(&Lp);
}
// convert float4 -> 4 bf16 hi + 4 bf16 lo, store 8B each
static __device__ __forceinline__ void cvt_store(__nv_bfloat16* ph,
                                                 __nv_bfloat16* pl, float4 v) {
    uint32_t h0, l0, h1, l1;
    split2(v.x, v.y, h0, l0);
    split2(v.z, v.w, h1, l1);
    *(uint2*)ph = make_uint2(h0, h1);
    *(uint2*)pl = make_uint2(l0, l1);
}

// ---------------------------------------------------------------------------
// fp32 -> bf16 hi/lo split. n must be a multiple of 1024. 256 thr * 4 elem.
// ---------------------------------------------------------------------------
__global__ __launch_bounds__(256) void split_bf16(const float* __restrict__ src,
                                                  __nv_bfloat16* __restrict__ hi,
                                                  __nv_bfloat16* __restrict__ lo,
                                                  int n)
{
    int i = (blockIdx.x * 256 + threadIdx.x) * 4;
    if (i >= n) return;
    float4 v = *(const float4*)(src + i);
    cvt_store(hi + i, lo + i, v);
}

// ---------------------------------------------------------------------------
// bf16x3 HMMA GEMM: O[M,N] = (Ah+Al)[M,K] @ (Wh+Wl)[N,K]^T  (fp32 out)
// CTA 128x128, BK=32. 256 thr = 8 warps (4x2); warp tile 32x64.
// ---------------------------------------------------------------------------
#define APITCH 40   // halves; 80 bytes (16B aligned)

__global__ __launch_bounds__(256) void gemm_mma(
    const __nv_bfloat16* __restrict__ Ah, const __nv_bfloat16* __restrict__ Al,
    const __nv_bfloat16* __restrict__ Wh, const __nv_bfloat16* __restrict__ Wl,
    float* __restrict__ O, int N, int K)
{
    __shared__ __nv_bfloat16 sAh[128][APITCH], sAl[128][APITCH];
    __shared__ __nv_bfloat16 sWh[128][APITCH], sWl[128][APITCH];

    const int tid  = threadIdx.x;
    const int lane = tid & 31, wid = tid >> 5;
    const int wm = wid >> 1, wn = wid & 1;          // 4x2 warp grid
    const int bm = blockIdx.y * 128, bn = blockIdx.x * 128;

    float acc[2][8][4];
#pragma unroll
    for (int mi = 0; mi < 2; mi++)
#pragma unroll
        for (int ni = 0; ni < 8; ni++)
#pragma unroll
            for (int e = 0; e < 4; e++) acc[mi][ni][e] = 0.0f;

    const __nv_bfloat16* pAh = Ah + (size_t)bm * K;
    const __nv_bfloat16* pAl = Al + (size_t)bm * K;
    const __nv_bfloat16* pWh = Wh + (size_t)bn * K;
    const __nv_bfloat16* pWl = Wl + (size_t)bn * K;

    const int ar = lane & 15, ac = (lane >> 4) << 3;
    const int bn_off = ((lane >> 4) << 3) + (lane & 7);
    const int bk_off = ((lane >> 3) & 1) << 3;

    for (int k0 = 0; k0 < K; k0 += 32) {
#pragma unroll
        for (int u = 0; u < 2; u++) {
            int r  = (tid >> 2) + u * 64;
            int cb = (tid & 3) << 3;
            size_t go = (size_t)r * K + k0 + cb;
            *(float4*)&sAh[r][cb] = *(const float4*)(pAh + go);
            *(float4*)&sAl[r][cb] = *(const float4*)(pAl + go);
            *(float4*)&sWh[r][cb] = *(const float4*)(pWh + go);
            *(float4*)&sWl[r][cb] = *(const float4*)(pWl + go);
        }
        __syncthreads();

#pragma unroll
        for (int ks = 0; ks < 2; ks++) {
            const int kk = ks * 16;
            uint32_t ah[2][4], al[2][4];
#pragma unroll
            for (int mi = 0; mi < 2; mi++) {
                int row = wm * 32 + mi * 16 + ar;
                ldm_x4(ah[mi], s2u(&sAh[row][kk + ac]));
                ldm_x4(al[mi], s2u(&sAl[row][kk + ac]));
            }
#pragma unroll
            for (int np = 0; np < 4; np++) {
                uint32_t bh[4], bl[4];
                int row = wn * 64 + np * 16 + bn_off;
                ldm_x4(bh, s2u(&sWh[row][kk + bk_off]));
                ldm_x4(bl, s2u(&sWl[row][kk + bk_off]));
#pragma unroll
                for (int mi = 0; mi < 2; mi++) {
                    mma_bf16(acc[mi][np*2],   ah[mi], bh[0], bh[1]);
                    mma_bf16(acc[mi][np*2+1], ah[mi], bh[2], bh[3]);
                    mma_bf16(acc[mi][np*2],   ah[mi], bl[0], bl[1]);
                    mma_bf16(acc[mi][np*2+1], ah[mi], bl[2], bl[3]);
                    mma_bf16(acc[mi][np*2],   al[mi], bh[0], bh[1]);
                    mma_bf16(acc[mi][np*2+1], al[mi], bh[2], bh[3]);
                }
            }
        }
        __syncthreads();
    }

#pragma unroll
    for (int mi = 0; mi < 2; mi++) {
#pragma unroll
        for (int ni = 0; ni < 8; ni++) {
            int row = bm + wm * 32 + mi * 16 + (lane >> 2);
            int col = bn + wn * 64 + ni * 8 + ((lane & 3) << 1);
            float2* o0 = (float2*)(O + (size_t)row * N + col);
            float2* o1 = (float2*)(O + (size_t)(row + 8) * N + col);
            *o0 = make_float2(acc[mi][ni][0], acc[mi][ni][1]);
            *o1 = make_float2(acc[mi][ni][2], acc[mi][ni][3]);
        }
    }
}

// ---------------------------------------------------------------------------
// Fused RoPE + RMSNorm, in place. One warp per head-vector (D=128).
// ---------------------------------------------------------------------------
__global__ __launch_bounds__(256) void rope_rms(float* __restrict__ v,
                                                const float* __restrict__ cosb,
                                                const float* __restrict__ sinb,
                                                int nheads, int total)
{
    int warp = (blockIdx.x * blockDim.x + threadIdx.x) >> 5;
    int lane = threadIdx.x & 31;
    if (warp >= total) return;

    int t = (warp / nheads) % T_;
    float* p = v + (size_t)warp * D_;

    float x0 = p[lane], x1 = p[lane + 32], x2 = p[lane + 64], x3 = p[lane + 96];
    const float* cp = cosb + (size_t)t * D_;
    const float* sp = sinb + (size_t)t * D_;
    float c0 = cp[lane], c1 = cp[lane + 32], c2 = cp[lane + 64], c3 = cp[lane + 96];
    float s0 = sp[lane], s1 = sp[lane + 32], s2 = sp[lane + 64], s3 = sp[lane + 96];

    float r0 = x0 * c0 - x2 * s0;
    float r1 = x1 * c1 - x3 * s1;
    float r2 = x2 * c2 + x0 * s2;
    float r3 = x3 * c3 + x1 * s3;

    float ss = r0 * r0 + r1 * r1 + r2 * r2 + r3 * r3;
#pragma unroll
    for (int off = 16; off; off >>= 1)
        ss += __shfl_xor_sync(0xffffffffu, ss, off);
    float inv = rsqrtf(ss * (1.0f / 128.0f) + 1.1920929e-7f);

    p[lane]      = r0 * inv;
    p[lane + 32] = r1 * inv;
    p[lane + 64] = r2 * inv;
    p[lane + 96] = r3 * inv;
}

// ---------------------------------------------------------------------------
// HMMA flash attention (bf16x3), causal, GQA.
// CTA = 128 queries of one (b,h); 8 warps, warp = 16 q-rows.
// Key tiles of 64. Q/K/V converted fp32->bf16 hi/lo in-kernel.
// S: QK^T 3 passes; softmax in regs; P hi/lo in regs; PV 3 passes.
// ---------------------------------------------------------------------------
#define AP 136   // smem pitch in halves (272 B, 16B-aligned rows)
#define ATT2_SMEM ((2*128 + 4*64) * AP * 2)   // 139264 bytes

__global__ __launch_bounds__(256) void attn_mma()
{
    extern __shared__ __nv_bfloat16 sm2[];
    __nv_bfloat16* Qh = sm2;               // [128][AP]
    __nv_bfloat16* Ql = Qh + 128 * AP;
    __nv_bfloat16* Kh = Ql + 128 * AP;     // [64][AP]
    __nv_bfloat16* Kl = Kh + 64 * AP;
    __nv_bfloat16* Vh = Kl + 64 * AP;
    __nv_bfloat16* Vl = Vh + 64 * AP;

    const int qt = (gridDim.x - 1) - blockIdx.x;   // heavy tiles first
    const int h = blockIdx.y, b = blockIdx.z;
    const int kvh = h >> 2;
    const int q0 = qt * 128;
    const int tid = threadIdx.x, lane = tid & 31, wid = tid >> 5;
    const float scale = 0.08838834764831845f;      // 1/sqrt(128)

    // ---- load Q tile fp32 -> bf16 hi/lo smem (persistent) ----
#pragma unroll
    for (int u = 0; u < 16; u++) {
        int fl = tid + u * 256;            // 0..4095
        int r = fl >> 5, c = (fl & 31) << 2;
        float4 qv = *(const float4*)(g_q +
            ((size_t)((b * T_ + q0 + r) * H_ + h)) * D_ + c);
        cvt_store(Qh + r * AP + c, Ql + r * AP + c, qv);
    }

    float m0 = -1e30f, m1 = -1e30f, l0 = 0.0f, l1 = 0.0f;
    float oacc[16][4];
#pragma unroll
    for (int t = 0; t < 16; t++)
#pragma unroll
        for (int e = 0; e < 4; e++) oacc[t][e] = 0.0f;

    const int ar  = lane & 15, ac = (lane >> 4) << 3;
    const int bno = ((lane >> 4) << 3) + (lane & 7);
    const int bko = ((lane >> 3) & 1) << 3;
    const int qrow = wid * 16 + ar;
    const int vro = lane & 15, vco = (lane >> 4) << 3;

    const int njt = 2 * qt + 2;
    for (int jt = 0; jt < njt; jt++) {
        const int j0 = jt * 64;
        // ---- load K,V fp32 -> bf16 hi/lo smem ----
#pragma unroll
        for (int u = 0; u < 8; u++) {
            int fl = tid + u * 256;        // 0..2047
            int r = fl >> 5, c = (fl & 31) << 2;
            size_t base = ((size_t)((b * T_ + j0 + r) * KVH_ + kvh)) * D_ + c;
            float4 kv = *(const float4*)(g_k + base);
            float4 vv = *(const float4*)(g_v + base);
            cvt_store(Kh + r * AP + c, Kl + r * AP + c, kv);
            cvt_store(Vh + r * AP + c, Vl + r * AP + c, vv);
        }
        __syncthreads();

        // ---- S = Q K^T, 3 passes (hh, hl, lh) ----
        float sacc[8][4];
#pragma unroll
        for (int nb = 0; nb < 8; nb++)
#pragma unroll
            for (int e = 0; e < 4; e++) sacc[nb][e] = 0.0f;

#pragma unroll
        for (int kc = 0; kc < 8; kc++) {
            uint32_t ah[4], al[4];
            ldm_x4(ah, s2u(Qh + qrow * AP + kc * 16 + ac));
            ldm_x4(al, s2u(Ql + qrow * AP + kc * 16 + ac));
#pragma unroll
            for (int nb = 0; nb < 4; nb++) {
                uint32_t bh[4], bl[4];
                int krow = nb * 16 + bno;
                ldm_x4(bh, s2u(Kh + krow * AP + kc * 16 + bko));
                ldm_x4(bl, s2u(Kl + krow * AP + kc * 16 + bko));
                mma_bf16(sacc[nb*2],   ah, bh[0], bh[1]);
                mma_bf16(sacc[nb*2+1], ah, bh[2], bh[3]);
                mma_bf16(sacc[nb*2],   ah, bl[0], bl[1]);
                mma_bf16(sacc[nb*2+1], ah, bl[2], bl[3]);
                mma_bf16(sacc[nb*2],   al, bh[0], bh[1]);
                mma_bf16(sacc[nb*2+1], al, bh[2], bh[3]);
            }
        }

        // ---- causal mask (only tiles touching the diagonal) ----
        if (jt >= 2 * qt) {
            int qi0 = q0 + wid * 16 + (lane >> 2);
            int kjb = j0 + ((lane & 3) << 1);
#pragma unroll
            for (int nb = 0; nb < 8; nb++) {
                int kj = kjb + nb * 8;
                if (kj     > qi0)     sacc[nb][0] = -1e30f;
                if (kj + 1 > qi0)     sacc[nb][1] = -1e30f;
                if (kj     > qi0 + 8) sacc[nb][2] = -1e30f;
                if (kj + 1 > qi0 + 8) sacc[nb][3] = -1e30f;
            }
        }

        // ---- online softmax (rows r = lane>>2 and r+8) ----
        float mx0 = -1e30f, mx1 = -1e30f;
#pragma unroll
        for (int nb = 0; nb < 8; nb++) {
            mx0 = fmaxf(mx0, fmaxf(sacc[nb][0], sacc[nb][1]));
            mx1 = fmaxf(mx1, fmaxf(sacc[nb][2], sacc[nb][3]));
        }
        mx0 = fmaxf(mx0, __shfl_xor_sync(0xffffffffu, mx0, 1));
        mx0 = fmaxf(mx0, __shfl_xor_sync(0xffffffffu, mx0, 2));
        mx1 = fmaxf(mx1, __shfl_xor_sync(0xffffffffu, mx1, 1));
        mx1 = fmaxf(mx1, __shfl_xor_sync(0xffffffffu, mx1, 2));
        float mn0 = fmaxf(m0, mx0), mn1 = fmaxf(m1, mx1);
        float al0 = __expf((m0 - mn0) * scale);
        float al1 = __expf((m1 - mn1) * scale);
        float s0 = 0.0f, s1 = 0.0f;
#pragma unroll
        for (int nb = 0; nb < 8; nb++) {
            float p0 = __expf((sacc[nb][0] - mn0) * scale);
            float p1 = __expf((sacc[nb][1] - mn0) * scale);
            float p2 = __expf((sacc[nb][2] - mn1) * scale);
            float p3 = __expf((sacc[nb][3] - mn1) * scale);
            sacc[nb][0] = p0; sacc[nb][1] = p1;
            sacc[nb][2] = p2; sacc[nb][3] = p3;
            s0 += p0 + p1;  s1 += p2 + p3;
        }
        s0 += __shfl_xor_sync(0xffffffffu, s0, 1);
        s0 += __shfl_xor_sync(0xffffffffu, s0, 2);
        s1 += __shfl_xor_sync(0xffffffffu, s1, 1);
        s1 += __shfl_xor_sync(0xffffffffu, s1, 2);
        l0 = l0 * al0 + s0;  l1 = l1 * al1 + s1;
        m0 = mn0;  m1 = mn1;
#pragma unroll
        for (int t = 0; t < 16; t++) {
            oacc[t][0] *= al0; oacc[t][1] *= al0;
            oacc[t][2] *= al1; oacc[t][3] *= al1;
        }

        // ---- O += P V, 3 passes (P hi/lo in regs; V via ldmatrix.trans) ----
#pragma unroll
        for (int kc = 0; kc < 4; kc++) {
            uint32_t aph[4], apl[4];
            split2(sacc[2*kc][0],   sacc[2*kc][1],   aph[0], apl[0]);
            split2(sacc[2*kc][2],   sacc[2*kc][3],   aph[1], apl[1]);
            split2(sacc[2*kc+1][0], sacc[2*kc+1][1], aph[2], apl[2]);
            split2(sacc[2*kc+1][2], sacc[2*kc+1][3], aph[3], apl[3]);
            int vrow = kc * 16 + vro;
#pragma unroll
            for (int nb = 0; nb < 8; nb++) {
                uint32_t bh[4], bl[4];
                ldm_x4_t(bh, s2u(Vh + vrow * AP + nb * 16 + vco));
                ldm_x4_t(bl, s2u(Vl + vrow * AP + nb * 16 + vco));
                mma_bf16(oacc[nb*2],   aph, bh[0], bh[1]);
                mma_bf16(oacc[nb*2+1], aph, bh[2], bh[3]);
                mma_bf16(oacc[nb*2],   aph, bl[0], bl[1]);
                mma_bf16(oacc[nb*2+1], aph, bl[2], bl[3]);
                mma_bf16(oacc[nb*2],   apl, bh[0], bh[1]);
                mma_bf16(oacc[nb*2+1], apl, bh[2], bh[3]);
            }
        }
        __syncthreads();
    }

    // ---- epilogue: normalize, write [B,T,H,D] fp32 ----
    float inv0 = 1.0f / l0, inv1 = 1.0f / l1;
    int r0 = q0 + wid * 16 + (lane >> 2);
    int col = (lane & 3) << 1;
#pragma unroll
    for (int t = 0; t < 16; t++) {
        float* d0 = g_att + ((size_t)((b * T_ + r0) * H_ + h)) * D_ + t * 8 + col;
        float* d1 = g_att + ((size_t)((b * T_ + r0 + 8) * H_ + h)) * D_ + t * 8 + col;
        *(float2*)d0 = make_float2(oacc[t][0] * inv0, oacc[t][1] * inv0);
        *(float2*)d1 = make_float2(oacc[t][2] * inv1, oacc[t][3] * inv1);
    }
}

// ---------------------------------------------------------------------------
extern "C" void kernel_launch(void* const* d_in, const int* in_sizes, int n_in,
                              void* d_out, int out_size)
{
    const float* x    = (const float*)d_in[0];
    const float* cosb = (const float*)d_in[1];
    const float* sinb = (const float*)d_in[2];
    const float* wq   = (const float*)d_in[3];
    const float* wk   = (const float*)d_in[4];
    const float* wv   = (const float*)d_in[5];
    const float* wp   = (const float*)d_in[6];
    float* out = (float*)d_out;

    float *q, *k, *v, *att;
    cudaGetSymbolAddress((void**)&q,   g_q);
    cudaGetSymbolAddress((void**)&k,   g_k);
    cudaGetSymbolAddress((void**)&v,   g_v);
    cudaGetSymbolAddress((void**)&att, g_att);

    __nv_bfloat16 *xh, *xl, *wqh, *wql, *wkh, *wkl, *wvh, *wvl, *wph, *wpl;
    cudaGetSymbolAddress((void**)&xh,  g_xh);
    cudaGetSymbolAddress((void**)&xl,  g_xl);
    cudaGetSymbolAddress((void**)&wqh, g_wqh);
    cudaGetSymbolAddress((void**)&wql, g_wql);
    cudaGetSymbolAddress((void**)&wkh, g_wkh);
    cudaGetSymbolAddress((void**)&wkl, g_wkl);
    cudaGetSymbolAddress((void**)&wvh, g_wvh);
    cudaGetSymbolAddress((void**)&wvl, g_wvl);
    cudaGetSymbolAddress((void**)&wph, g_wph);
    cudaGetSymbolAddress((void**)&wpl, g_wpl);

    cudaFuncSetAttribute(attn_mma,
                         cudaFuncAttributeMaxDynamicSharedMemorySize, ATT2_SMEM);

    // fp32 -> bf16 hi/lo splits
    split_bf16<<<(M_*C_) / 1024, 256>>>(x,  xh,  xl,  M_*C_);
    split_bf16<<<(2048*2048) / 1024, 256>>>(wq, wqh, wql, 2048*2048);
    split_bf16<<<(512*2048) / 1024, 256>>>(wk, wkh, wkl, 512*2048);
    split_bf16<<<(512*2048) / 1024, 256>>>(wv, wvh, wvl, 512*2048);
    split_bf16<<<(2048*2048) / 1024, 256>>>(wp, wph, wpl, 2048*2048);

    // QKV projections (HMMA bf16x3)
    gemm_mma<<<dim3(2048/128, M_/128), 256>>>(xh, xl, wqh, wql, q, 2048, C_);
    gemm_mma<<<dim3(512/128,  M_/128), 256>>>(xh, xl, wkh, wkl, k, 512,  C_);
    gemm_mma<<<dim3(512/128,  M_/128), 256>>>(xh, xl, wvh, wvl, v, 512,  C_);

    // RoPE + RMSNorm (in place, fp32)
    {
        int totq = B_ * T_ * H_;
        int totk = B_ * T_ * KVH_;
        rope_rms<<<(totq + 7) / 8, 256>>>(q, cosb, sinb, H_,   totq);
        rope_rms<<<(totk + 7) / 8, 256>>>(k, cosb, sinb, KVH_, totk);
    }

    // HMMA flash attention
    attn_mma<<<dim3(T_ / 128, H_, B_), 256, ATT2_SMEM>>>();

    // Output projection: split attention output (reuse x split buffers), then GEMM
    split_bf16<<<(M_*C_) / 1024, 256>>>(att, xh, xl, M_*C_);
    gemm_mma<<<dim3(2048/128, M_/128), 256>>>(xh, xl, wph, wpl, out, 2048, C_);
}

// round 13
// speedup vs baseline: 2.7901x; 1.4734x over previous
#include <cuda_runtime.h>
#include <cuda_bf16.h>
#include <cstdint>
#include <math.h>

#define B_    2
#define T_    2048
#define C_    2048
#define H_    16
#define KVH_  4
#define D_    128
#define M_    (B_*T_)      // 4096

// ---------------------------------------------------------------------------
// Scratch (static device globals: allocation-guard safe)
// ---------------------------------------------------------------------------
__device__ float g_q[(size_t)B_*T_*H_*D_];     // fp32 gemm outputs
__device__ float g_k[(size_t)B_*T_*KVH_*D_];
__device__ float g_v[(size_t)B_*T_*KVH_*D_];

// bf16 hi/lo operand buffers
__device__ __nv_bfloat16 g_xh[(size_t)M_*C_];   // x split; reused for att output
__device__ __nv_bfloat16 g_xl[(size_t)M_*C_];
__device__ __nv_bfloat16 g_qh[(size_t)B_*T_*H_*D_],   g_ql[(size_t)B_*T_*H_*D_];
__device__ __nv_bfloat16 g_kh[(size_t)B_*T_*KVH_*D_], g_kl[(size_t)B_*T_*KVH_*D_];
__device__ __nv_bfloat16 g_vh[(size_t)B_*T_*KVH_*D_], g_vl[(size_t)B_*T_*KVH_*D_];
__device__ __nv_bfloat16 g_wqh[(size_t)2048*2048], g_wql[(size_t)2048*2048];
__device__ __nv_bfloat16 g_wkh[(size_t)512*2048],  g_wkl[(size_t)512*2048];
__device__ __nv_bfloat16 g_wvh[(size_t)512*2048],  g_wvl[(size_t)512*2048];
__device__ __nv_bfloat16 g_wph[(size_t)2048*2048], g_wpl[(size_t)2048*2048];

// ---------------------------------------------------------------------------
// PTX helpers (sm_80-era: compile for plain compute_103)
// ---------------------------------------------------------------------------
static __device__ __forceinline__ uint32_t s2u(const void* p) {
    return (uint32_t)__cvta_generic_to_shared(p);
}
static __device__ __forceinline__ void ldm_x4(uint32_t* r, uint32_t addr) {
    asm volatile("ldmatrix.sync.aligned.m8n8.x4.shared.b16 {%0,%1,%2,%3}, [%4];"
                 : "=r"(r[0]), "=r"(r[1]), "=r"(r[2]), "=r"(r[3]) : "r"(addr));
}
static __device__ __forceinline__ void ldm_x4_t(uint32_t* r, uint32_t addr) {
    asm volatile("ldmatrix.sync.aligned.m8n8.x4.trans.shared.b16 {%0,%1,%2,%3}, [%4];"
                 : "=r"(r[0]), "=r"(r[1]), "=r"(r[2]), "=r"(r[3]) : "r"(addr));
}
static __device__ __forceinline__ void mma_bf16(float* d, const uint32_t* a,
                                                uint32_t b0, uint32_t b1) {
    asm volatile(
        "mma.sync.aligned.m16n8k16.row.col.f32.bf16.bf16.f32 "
        "{%0,%1,%2,%3}, {%4,%5,%6,%7}, {%8,%9}, {%0,%1,%2,%3};"
        : "+f"(d[0]), "+f"(d[1]), "+f"(d[2]), "+f"(d[3])
        : "r"(a[0]), "r"(a[1]), "r"(a[2]), "r"(a[3]), "r"(b0), "r"(b1));
}
static __device__ __forceinline__ void cp16(uint32_t dst, const void* src) {
    asm volatile("cp.async.cg.shared.global [%0], [%1], 16;"
                 :: "r"(dst), "l"(src) : "memory");
}
static __device__ __forceinline__ void cp_commit() {
    asm volatile("cp.async.commit_group;" ::: "memory");
}
template<int N> static __device__ __forceinline__ void cp_wait() {
    asm volatile("cp.async.wait_group %0;" :: "n"(N) : "memory");
}
// pack two floats as bf16x2 hi/lo split
static __device__ __forceinline__ void split2(float x, float y,
                                              uint32_t& hi, uint32_t& lo) {
    __nv_bfloat16 hx = __float2bfloat16(x), hy = __float2bfloat16(y);
    __nv_bfloat16 lx = __float2bfloat16(x - __bfloat162float(hx));
    __nv_bfloat16 ly = __float2bfloat16(y - __bfloat162float(hy));
    __nv_bfloat162 Hp; Hp.x = hx; Hp.y = hy;
    __nv_bfloat162 Lp; Lp.x = lx; Lp.y = ly;
    hi = *reinterpret_cast<uint32_t*>(&Hp);
    lo = *reinterpret_cast<uint32_t*>(&Lp);
}
static __device__ __forceinline__ void cvt_store(__nv_bfloat16* ph,
                                                 __nv_bfloat16* pl, float4 v) {
    uint32_t h0, l0, h1, l1;
    split2(v.x, v.y, h0, l0);
    split2(v.z, v.w, h1, l1);
    *(uint2*)ph = make_uint2(h0, h1);
    *(uint2*)pl = make_uint2(l0, l1);
}

// ---------------------------------------------------------------------------
// fp32 -> bf16 hi/lo split. n multiple of 1024.
// ---------------------------------------------------------------------------
__global__ __launch_bounds__(256) void split_bf16(const float* __restrict__ src,
                                                  __nv_bfloat16* __restrict__ hi,
                                                  __nv_bfloat16* __restrict__ lo,
                                                  int n)
{
    int i = (blockIdx.x * 256 + threadIdx.x) * 4;
    if (i >= n) return;
    float4 v = *(const float4*)(src + i);
    cvt_store(hi + i, lo + i, v);
}

// ---------------------------------------------------------------------------
// bf16x3 HMMA GEMM (unchanged): O[M,N] = (Ah+Al)[M,K] @ (Wh+Wl)[N,K]^T
// ---------------------------------------------------------------------------
#define APITCH 40

__global__ __launch_bounds__(256) void gemm_mma(
    const __nv_bfloat16* __restrict__ Ah, const __nv_bfloat16* __restrict__ Al,
    const __nv_bfloat16* __restrict__ Wh, const __nv_bfloat16* __restrict__ Wl,
    float* __restrict__ O, int N, int K)
{
    __shared__ __nv_bfloat16 sAh[128][APITCH], sAl[128][APITCH];
    __shared__ __nv_bfloat16 sWh[128][APITCH], sWl[128][APITCH];

    const int tid  = threadIdx.x;
    const int lane = tid & 31, wid = tid >> 5;
    const int wm = wid >> 1, wn = wid & 1;
    const int bm = blockIdx.y * 128, bn = blockIdx.x * 128;

    float acc[2][8][4];
#pragma unroll
    for (int mi = 0; mi < 2; mi++)
#pragma unroll
        for (int ni = 0; ni < 8; ni++)
#pragma unroll
            for (int e = 0; e < 4; e++) acc[mi][ni][e] = 0.0f;

    const __nv_bfloat16* pAh = Ah + (size_t)bm * K;
    const __nv_bfloat16* pAl = Al + (size_t)bm * K;
    const __nv_bfloat16* pWh = Wh + (size_t)bn * K;
    const __nv_bfloat16* pWl = Wl + (size_t)bn * K;

    const int ar = lane & 15, ac = (lane >> 4) << 3;
    const int bn_off = ((lane >> 4) << 3) + (lane & 7);
    const int bk_off = ((lane >> 3) & 1) << 3;

    for (int k0 = 0; k0 < K; k0 += 32) {
#pragma unroll
        for (int u = 0; u < 2; u++) {
            int r  = (tid >> 2) + u * 64;
            int cb = (tid & 3) << 3;
            size_t go = (size_t)r * K + k0 + cb;
            *(float4*)&sAh[r][cb] = *(const float4*)(pAh + go);
            *(float4*)&sAl[r][cb] = *(const float4*)(pAl + go);
            *(float4*)&sWh[r][cb] = *(const float4*)(pWh + go);
            *(float4*)&sWl[r][cb] = *(const float4*)(pWl + go);
        }
        __syncthreads();

#pragma unroll
        for (int ks = 0; ks < 2; ks++) {
            const int kk = ks * 16;
            uint32_t ah[2][4], al[2][4];
#pragma unroll
            for (int mi = 0; mi < 2; mi++) {
                int row = wm * 32 + mi * 16 + ar;
                ldm_x4(ah[mi], s2u(&sAh[row][kk + ac]));
                ldm_x4(al[mi], s2u(&sAl[row][kk + ac]));
            }
#pragma unroll
            for (int np = 0; np < 4; np++) {
                uint32_t bh[4], bl[4];
                int row = wn * 64 + np * 16 + bn_off;
                ldm_x4(bh, s2u(&sWh[row][kk + bk_off]));
                ldm_x4(bl, s2u(&sWl[row][kk + bk_off]));
#pragma unroll
                for (int mi = 0; mi < 2; mi++) {
                    mma_bf16(acc[mi][np*2],   ah[mi], bh[0], bh[1]);
                    mma_bf16(acc[mi][np*2+1], ah[mi], bh[2], bh[3]);
                    mma_bf16(acc[mi][np*2],   ah[mi], bl[0], bl[1]);
                    mma_bf16(acc[mi][np*2+1], ah[mi], bl[2], bl[3]);
                    mma_bf16(acc[mi][np*2],   al[mi], bh[0], bh[1]);
                    mma_bf16(acc[mi][np*2+1], al[mi], bh[2], bh[3]);
                }
            }
        }
        __syncthreads();
    }

#pragma unroll
    for (int mi = 0; mi < 2; mi++) {
#pragma unroll
        for (int ni = 0; ni < 8; ni++) {
            int row = bm + wm * 32 + mi * 16 + (lane >> 2);
            int col = bn + wn * 64 + ni * 8 + ((lane & 3) << 1);
            float2* o0 = (float2*)(O + (size_t)row * N + col);
            float2* o1 = (float2*)(O + (size_t)(row + 8) * N + col);
            *o0 = make_float2(acc[mi][ni][0], acc[mi][ni][1]);
            *o1 = make_float2(acc[mi][ni][2], acc[mi][ni][3]);
        }
    }
}

// ---------------------------------------------------------------------------
// Fused RoPE + RMSNorm + scale + bf16 hi/lo split. One warp per head-vector.
// Writes bf16 hi/lo (outscale folds softmax scale*log2e into Q).
// ---------------------------------------------------------------------------
__global__ __launch_bounds__(256) void rope_rms_split(
    const float* __restrict__ v,
    __nv_bfloat16* __restrict__ oh, __nv_bfloat16* __restrict__ ol,
    const float* __restrict__ cosb, const float* __restrict__ sinb,
    int nheads, int total, float outscale)
{
    int warp = (blockIdx.x * blockDim.x + threadIdx.x) >> 5;
    int lane = threadIdx.x & 31;
    if (warp >= total) return;

    int t = (warp / nheads) % T_;
    const float* p = v + (size_t)warp * D_;

    float x0 = p[lane], x1 = p[lane + 32], x2 = p[lane + 64], x3 = p[lane + 96];
    const float* cp = cosb + (size_t)t * D_;
    const float* sp = sinb + (size_t)t * D_;
    float c0 = cp[lane], c1 = cp[lane + 32], c2 = cp[lane + 64], c3 = cp[lane + 96];
    float s0 = sp[lane], s1 = sp[lane + 32], s2 = sp[lane + 64], s3 = sp[lane + 96];

    float r0 = x0 * c0 - x2 * s0;
    float r1 = x1 * c1 - x3 * s1;
    float r2 = x2 * c2 + x0 * s2;
    float r3 = x3 * c3 + x1 * s3;

    float ss = r0 * r0 + r1 * r1 + r2 * r2 + r3 * r3;
#pragma unroll
    for (int off = 16; off; off >>= 1)
        ss += __shfl_xor_sync(0xffffffffu, ss, off);
    float inv = rsqrtf(ss * (1.0f / 128.0f) + 1.1920929e-7f) * outscale;

    __nv_bfloat16* ph = oh + (size_t)warp * D_;
    __nv_bfloat16* pl = ol + (size_t)warp * D_;
    float o0 = r0 * inv, o1 = r1 * inv, o2 = r2 * inv, o3 = r3 * inv;
    __nv_bfloat16 h;
    h = __float2bfloat16(o0); ph[lane]      = h; pl[lane]      = __float2bfloat16(o0 - __bfloat162float(h));
    h = __float2bfloat16(o1); ph[lane + 32] = h; pl[lane + 32] = __float2bfloat16(o1 - __bfloat162float(h));
    h = __float2bfloat16(o2); ph[lane + 64] = h; pl[lane + 64] = __float2bfloat16(o2 - __bfloat162float(h));
    h = __float2bfloat16(o3); ph[lane + 96] = h; pl[lane + 96] = __float2bfloat16(o3 - __bfloat162float(h));
}

// ---------------------------------------------------------------------------
// HMMA flash attention (bf16x3), causal, GQA. bf16 inputs; cp.async 2-stage
// K/V pipeline; exp2 softmax (scale*log2e folded into Q); bf16 hi/lo output.
// CTA = 128 queries of one (b,h); 8 warps. Key tiles of 64.
// ---------------------------------------------------------------------------
#define AP 136                              // smem pitch in halves
#define STAGEH (4 * 64 * AP)                // halves per KV stage
#define ATT3_SMEM ((2*128*AP + 2*STAGEH) * 2)   // 208896 bytes

__global__ __launch_bounds__(256) void attn_mma()
{
    extern __shared__ __nv_bfloat16 sm2[];
    __nv_bfloat16* Qh = sm2;               // [128][AP]
    __nv_bfloat16* Ql = Qh + 128 * AP;
    __nv_bfloat16* KV = Ql + 128 * AP;     // 2 stages x {Kh,Kl,Vh,Vl}[64][AP]

    const int qt = (gridDim.x - 1) - blockIdx.x;   // heavy tiles first
    const int h = blockIdx.y, b = blockIdx.z;
    const int kvh = h >> 2;
    const int q0 = qt * 128;
    const int tid = threadIdx.x, lane = tid & 31, wid = tid >> 5;

    const __nv_bfloat16* gq[2] = {
        g_qh + ((size_t)((b * T_ + q0) * H_ + h)) * D_,
        g_ql + ((size_t)((b * T_ + q0) * H_ + h)) * D_ };
    // ---- load Q tile (persistent, plain vector loads) ----
#pragma unroll
    for (int u = 0; u < 16; u++) {
        int fl = u * 256 + tid;            // 0..4095
        int bf = u >> 3;                   // 0:hi 1:lo (static)
        int rem = fl & 2047;
        int r = rem >> 4, c = (rem & 15) * 8;
        uint4 qv = *(const uint4*)(gq[bf] + (size_t)r * (H_ * D_) + c);
        *(uint4*)((bf ? Ql : Qh) + r * AP + c) = qv;
    }

    // KV global row bases (row stride = KVH_*D_ elements)
    const size_t kvrow = (size_t)KVH_ * D_;
    const __nv_bfloat16* gkv[4] = {
        g_kh + ((size_t)(b * T_) * KVH_ + kvh) * D_,
        g_kl + ((size_t)(b * T_) * KVH_ + kvh) * D_,
        g_vh + ((size_t)(b * T_) * KVH_ + kvh) * D_,
        g_vl + ((size_t)(b * T_) * KVH_ + kvh) * D_ };

    const int njt = 2 * qt + 2;

    // issue cp.async for one stage
    auto issue = [&](int stage, int j0) {
        __nv_bfloat16* base = KV + stage * STAGEH;
#pragma unroll
        for (int u = 0; u < 16; u++) {
            int bf = u >> 2;                       // buffer 0..3 (static)
            int rem = (u & 3) * 256 + tid;         // 0..1023
            int r = rem >> 4, c = (rem & 15) * 8;
            cp16(s2u(base + bf * 64 * AP + r * AP + c),
                 gkv[bf] + (size_t)(j0 + r) * kvrow + c);
        }
    };

    issue(0, 0);
    cp_commit();

    float m0 = -1e30f, m1 = -1e30f, l0 = 0.0f, l1 = 0.0f;
    float oacc[16][4];
#pragma unroll
    for (int t = 0; t < 16; t++)
#pragma unroll
        for (int e = 0; e < 4; e++) oacc[t][e] = 0.0f;

    const int ar  = lane & 15, ac = (lane >> 4) << 3;
    const int bno = ((lane >> 4) << 3) + (lane & 7);
    const int bko = ((lane >> 3) & 1) << 3;
    const int qrow = wid * 16 + ar;
    const int vro = lane & 15, vco = (lane >> 4) << 3;

    for (int jt = 0; jt < njt; jt++) {
        const int j0 = jt * 64;
        if (jt + 1 < njt) {
            issue((jt + 1) & 1, j0 + 64);
            cp_commit();
            cp_wait<1>();
        } else {
            cp_wait<0>();
        }
        __syncthreads();

        __nv_bfloat16* Kh = KV + (jt & 1) * STAGEH;
        __nv_bfloat16* Kl = Kh + 64 * AP;
        __nv_bfloat16* Vh = Kl + 64 * AP;
        __nv_bfloat16* Vl = Vh + 64 * AP;

        // ---- S = Q K^T, 3 passes (hh, hl, lh) ----
        float sacc[8][4];
#pragma unroll
        for (int nb = 0; nb < 8; nb++)
#pragma unroll
            for (int e = 0; e < 4; e++) sacc[nb][e] = 0.0f;

#pragma unroll
        for (int kc = 0; kc < 8; kc++) {
            uint32_t ah[4], al[4];
            ldm_x4(ah, s2u(Qh + qrow * AP + kc * 16 + ac));
            ldm_x4(al, s2u(Ql + qrow * AP + kc * 16 + ac));
#pragma unroll
            for (int nb = 0; nb < 4; nb++) {
                uint32_t bh[4], bl[4];
                int krow = nb * 16 + bno;
                ldm_x4(bh, s2u(Kh + krow * AP + kc * 16 + bko));
                ldm_x4(bl, s2u(Kl + krow * AP + kc * 16 + bko));
                mma_bf16(sacc[nb*2],   ah, bh[0], bh[1]);
                mma_bf16(sacc[nb*2+1], ah, bh[2], bh[3]);
                mma_bf16(sacc[nb*2],   ah, bl[0], bl[1]);
                mma_bf16(sacc[nb*2+1], ah, bl[2], bl[3]);
                mma_bf16(sacc[nb*2],   al, bh[0], bh[1]);
                mma_bf16(sacc[nb*2+1], al, bh[2], bh[3]);
            }
        }

        // ---- causal mask (only the two diagonal-touching tiles) ----
        if (jt >= 2 * qt) {
            int qi0 = q0 + wid * 16 + (lane >> 2);
            int kjb = j0 + ((lane & 3) << 1);
#pragma unroll
            for (int nb = 0; nb < 8; nb++) {
                int kj = kjb + nb * 8;
                if (kj     > qi0)     sacc[nb][0] = -1e30f;
                if (kj + 1 > qi0)     sacc[nb][1] = -1e30f;
                if (kj     > qi0 + 8) sacc[nb][2] = -1e30f;
                if (kj + 1 > qi0 + 8) sacc[nb][3] = -1e30f;
            }
        }

        // ---- online softmax in exp2 domain (S already scaled) ----
        float mx0 = -1e30f, mx1 = -1e30f;
#pragma unroll
        for (int nb = 0; nb < 8; nb++) {
            mx0 = fmaxf(mx0, fmaxf(sacc[nb][0], sacc[nb][1]));
            mx1 = fmaxf(mx1, fmaxf(sacc[nb][2], sacc[nb][3]));
        }
        mx0 = fmaxf(mx0, __shfl_xor_sync(0xffffffffu, mx0, 1));
        mx0 = fmaxf(mx0, __shfl_xor_sync(0xffffffffu, mx0, 2));
        mx1 = fmaxf(mx1, __shfl_xor_sync(0xffffffffu, mx1, 1));
        mx1 = fmaxf(mx1, __shfl_xor_sync(0xffffffffu, mx1, 2));
        float mn0 = fmaxf(m0, mx0), mn1 = fmaxf(m1, mx1);
        float al0 = exp2f(m0 - mn0);
        float al1 = exp2f(m1 - mn1);
        float s0 = 0.0f, s1 = 0.0f;
#pragma unroll
        for (int nb = 0; nb < 8; nb++) {
            float p0 = exp2f(sacc[nb][0] - mn0);
            float p1 = exp2f(sacc[nb][1] - mn0);
            float p2 = exp2f(sacc[nb][2] - mn1);
            float p3 = exp2f(sacc[nb][3] - mn1);
            sacc[nb][0] = p0; sacc[nb][1] = p1;
            sacc[nb][2] = p2; sacc[nb][3] = p3;
            s0 += p0 + p1;  s1 += p2 + p3;
        }
        s0 += __shfl_xor_sync(0xffffffffu, s0, 1);
        s0 += __shfl_xor_sync(0xffffffffu, s0, 2);
        s1 += __shfl_xor_sync(0xffffffffu, s1, 1);
        s1 += __shfl_xor_sync(0xffffffffu, s1, 2);
        l0 = l0 * al0 + s0;  l1 = l1 * al1 + s1;
        m0 = mn0;  m1 = mn1;
#pragma unroll
        for (int t = 0; t < 16; t++) {
            oacc[t][0] *= al0; oacc[t][1] *= al0;
            oacc[t][2] *= al1; oacc[t][3] *= al1;
        }

        // ---- O += P V, 3 passes (P hi/lo in regs; V via ldmatrix.trans) ----
#pragma unroll
        for (int kc = 0; kc < 4; kc++) {
            uint32_t aph[4], apl[4];
            split2(sacc[2*kc][0],   sacc[2*kc][1],   aph[0], apl[0]);
            split2(sacc[2*kc][2],   sacc[2*kc][3],   aph[1], apl[1]);
            split2(sacc[2*kc+1][0], sacc[2*kc+1][1], aph[2], apl[2]);
            split2(sacc[2*kc+1][2], sacc[2*kc+1][3], aph[3], apl[3]);
            int vrow = kc * 16 + vro;
#pragma unroll
            for (int nb = 0; nb < 8; nb++) {
                uint32_t bh[4], bl[4];
                ldm_x4_t(bh, s2u(Vh + vrow * AP + nb * 16 + vco));
                ldm_x4_t(bl, s2u(Vl + vrow * AP + nb * 16 + vco));
                mma_bf16(oacc[nb*2],   aph, bh[0], bh[1]);
                mma_bf16(oacc[nb*2+1], aph, bh[2], bh[3]);
                mma_bf16(oacc[nb*2],   aph, bl[0], bl[1]);
                mma_bf16(oacc[nb*2+1], aph, bl[2], bl[3]);
                mma_bf16(oacc[nb*2],   apl, bh[0], bh[1]);
                mma_bf16(oacc[nb*2+1], apl, bh[2], bh[3]);
            }
        }
        __syncthreads();
    }

    // ---- epilogue: normalize, split to bf16 hi/lo proj input buffers ----
    float inv0 = 1.0f / l0, inv1 = 1.0f / l1;
    int r0 = q0 + wid * 16 + (lane >> 2);
    int col = (lane & 3) << 1;
#pragma unroll
    for (int t = 0; t < 16; t++) {
        size_t i0 = ((size_t)((b * T_ + r0) * H_ + h)) * D_ + t * 8 + col;
        size_t i1 = ((size_t)((b * T_ + r0 + 8) * H_ + h)) * D_ + t * 8 + col;
        uint32_t hi, lo;
        split2(oacc[t][0] * inv0, oacc[t][1] * inv0, hi, lo);
        *(uint32_t*)(g_xh + i0) = hi;
        *(uint32_t*)(g_xl + i0) = lo;
        split2(oacc[t][2] * inv1, oacc[t][3] * inv1, hi, lo);
        *(uint32_t*)(g_xh + i1) = hi;
        *(uint32_t*)(g_xl + i1) = lo;
    }
}

// ---------------------------------------------------------------------------
extern "C" void kernel_launch(void* const* d_in, const int* in_sizes, int n_in,
                              void* d_out, int out_size)
{
    const float* x    = (const float*)d_in[0];
    const float* cosb = (const float*)d_in[1];
    const float* sinb = (const float*)d_in[2];
    const float* wq   = (const float*)d_in[3];
    const float* wk   = (const float*)d_in[4];
    const float* wv   = (const float*)d_in[5];
    const float* wp   = (const float*)d_in[6];
    float* out = (float*)d_out;

    float *q, *k, *v;
    cudaGetSymbolAddress((void**)&q, g_q);
    cudaGetSymbolAddress((void**)&k, g_k);
    cudaGetSymbolAddress((void**)&v, g_v);

    __nv_bfloat16 *xh, *xl, *qh, *ql, *kh, *kl, *vh, *vl;
    __nv_bfloat16 *wqh, *wql, *wkh, *wkl, *wvh, *wvl, *wph, *wpl;
    cudaGetSymbolAddress((void**)&xh,  g_xh);
    cudaGetSymbolAddress((void**)&xl,  g_xl);
    cudaGetSymbolAddress((void**)&qh,  g_qh);
    cudaGetSymbolAddress((void**)&ql,  g_ql);
    cudaGetSymbolAddress((void**)&kh,  g_kh);
    cudaGetSymbolAddress((void**)&kl,  g_kl);
    cudaGetSymbolAddress((void**)&vh,  g_vh);
    cudaGetSymbolAddress((void**)&vl,  g_vl);
    cudaGetSymbolAddress((void**)&wqh, g_wqh);
    cudaGetSymbolAddress((void**)&wql, g_wql);
    cudaGetSymbolAddress((void**)&wkh, g_wkh);
    cudaGetSymbolAddress((void**)&wkl, g_wkl);
    cudaGetSymbolAddress((void**)&wvh, g_wvh);
    cudaGetSymbolAddress((void**)&wvl, g_wvl);
    cudaGetSymbolAddress((void**)&wph, g_wph);
    cudaGetSymbolAddress((void**)&wpl, g_wpl);

    cudaFuncSetAttribute(attn_mma,
                         cudaFuncAttributeMaxDynamicSharedMemorySize, ATT3_SMEM);

    // fp32 -> bf16 hi/lo splits of x and weights
    split_bf16<<<(M_*C_) / 1024, 256>>>(x,  xh,  xl,  M_*C_);
    split_bf16<<<(2048*2048) / 1024, 256>>>(wq, wqh, wql, 2048*2048);
    split_bf16<<<(512*2048) / 1024, 256>>>(wk, wkh, wkl, 512*2048);
    split_bf16<<<(512*2048) / 1024, 256>>>(wv, wvh, wvl, 512*2048);
    split_bf16<<<(2048*2048) / 1024, 256>>>(wp, wph, wpl, 2048*2048);

    // QKV projections (HMMA bf16x3)
    gemm_mma<<<dim3(2048/128, M_/128), 256>>>(xh, xl, wqh, wql, q, 2048, C_);
    gemm_mma<<<dim3(512/128,  M_/128), 256>>>(xh, xl, wkh, wkl, k, 512,  C_);
    gemm_mma<<<dim3(512/128,  M_/128), 256>>>(xh, xl, wvh, wvl, v, 512,  C_);

    // RoPE + RMSNorm + bf16 split. Q folds softmax scale * log2(e).
    {
        const float qscale = 0.08838834764831845f * 1.4426950408889634f;
        int totq = B_ * T_ * H_;
        int totk = B_ * T_ * KVH_;
        rope_rms_split<<<(totq + 7) / 8, 256>>>(q, qh, ql, cosb, sinb, H_,   totq, qscale);
        rope_rms_split<<<(totk + 7) / 8, 256>>>(k, kh, kl, cosb, sinb, KVH_, totk, 1.0f);
        split_bf16<<<(B_*T_*KVH_*D_) / 1024, 256>>>(v, vh, vl, B_*T_*KVH_*D_);
    }

    // HMMA flash attention -> writes bf16 hi/lo directly into xh/xl
    attn_mma<<<dim3(T_ / 128, H_, B_), 256, ATT3_SMEM>>>();

    // Output projection
    gemm_mma<<<dim3(2048/128, M_/128), 256>>>(xh, xl, wph, wpl, out, 2048, C_);
}